// round 7
// baseline (speedup 1.0000x reference)
#include <cuda_runtime.h>
#include <cstddef>
#include <math.h>

// Problem constants
#define BB 32
#define SS 512
#define DD 512
#define HH 512
#define G4 (4 * HH)   // 2048
#define NBLK 128      // persistent grid size (1 CTA/SM, all co-resident)

// ---------------------------------------------------------------------------
// Scratch (static __device__ arrays — no allocation allowed)
// ---------------------------------------------------------------------------
__device__ float g_xp[2][BB][SS][G4];      // per-direction input projections
__device__ float g_out0[BB][SS][2 * HH];   // layer-0 output
__device__ float g_h[2][2][BB][HH];        // [dir][parity][b][h]
__device__ unsigned g_bar_count;
__device__ volatile unsigned g_bar_sense;

// ---------------------------------------------------------------------------
// Zero h state + barrier vars
// ---------------------------------------------------------------------------
__global__ void __launch_bounds__(256) init_state_kernel()
{
    int i = blockIdx.x * 256 + threadIdx.x;
    if (i < 2 * 2 * BB * HH) (&g_h[0][0][0][0])[i] = 0.0f;
    if (i == 0) { g_bar_count = 0; g_bar_sense = 0; }
}

// ---------------------------------------------------------------------------
// GEMM: out[m][n] = sum_k A(m,k) * W[n][k] + bias[n]   (verified in R5)
// Tile: 128(m) x 64(n) x 16(k), 256 threads, 8x4 micro-tile, 1-tile prefetch.
// ---------------------------------------------------------------------------
__global__ void __launch_bounds__(256) gemm_xp_kernel(
    const float* __restrict__ A, long sAb, long sAs, int K,
    const float* __restrict__ W, const float* __restrict__ bias,
    float* __restrict__ out)
{
    __shared__ float As[16][132];
    __shared__ float Bs[16][68];

    const int tid = threadIdx.x;
    const int m0 = blockIdx.y * 128;
    const int n0 = blockIdx.x * 64;

    const int ar  = tid >> 1;
    const int ak  = (tid & 1) * 8;
    const int am  = m0 + ar;
    const int ab  = am >> 9;
    const int asd = am & 511;
    const float* Ap = A + (size_t)ab * sAb + (size_t)asd * sAs + ak;

    const int br = tid >> 2;
    const int bk = (tid & 3) * 4;
    const float* Wp = W + (size_t)(n0 + br) * K + bk;

    const int tx = tid & 15;
    const int ty = tid >> 4;

    float acc[8][4];
#pragma unroll
    for (int i = 0; i < 8; i++)
#pragma unroll
        for (int j = 0; j < 4; j++) acc[i][j] = 0.0f;

    float4 a0 = *(const float4*)(Ap + 0);
    float4 a1 = *(const float4*)(Ap + 4);
    float4 bv = *(const float4*)(Wp + 0);

    for (int k0 = 0; k0 < K; k0 += 16) {
        As[ak + 0][ar] = a0.x; As[ak + 1][ar] = a0.y; As[ak + 2][ar] = a0.z; As[ak + 3][ar] = a0.w;
        As[ak + 4][ar] = a1.x; As[ak + 5][ar] = a1.y; As[ak + 6][ar] = a1.z; As[ak + 7][ar] = a1.w;
        Bs[bk + 0][br] = bv.x; Bs[bk + 1][br] = bv.y; Bs[bk + 2][br] = bv.z; Bs[bk + 3][br] = bv.w;
        __syncthreads();

        if (k0 + 16 < K) {
            a0 = *(const float4*)(Ap + k0 + 16);
            a1 = *(const float4*)(Ap + k0 + 20);
            bv = *(const float4*)(Wp + k0 + 16);
        }

#pragma unroll
        for (int k = 0; k < 16; k++) {
            float4 A0 = *(const float4*)&As[k][ty * 8];
            float4 A1 = *(const float4*)&As[k][ty * 8 + 4];
            float4 Bv = *(const float4*)&Bs[k][tx * 4];
            float a8[8] = {A0.x, A0.y, A0.z, A0.w, A1.x, A1.y, A1.z, A1.w};
            float b4[4] = {Bv.x, Bv.y, Bv.z, Bv.w};
#pragma unroll
            for (int i = 0; i < 8; i++)
#pragma unroll
                for (int j = 0; j < 4; j++) acc[i][j] += a8[i] * b4[j];
        }
        __syncthreads();
    }

    float4 bs4 = *(const float4*)(bias + n0 + tx * 4);
#pragma unroll
    for (int i = 0; i < 8; i++) {
        int m = m0 + ty * 8 + i;
        float4 v;
        v.x = acc[i][0] + bs4.x;
        v.y = acc[i][1] + bs4.y;
        v.z = acc[i][2] + bs4.z;
        v.w = acc[i][3] + bs4.w;
        *(float4*)(out + (size_t)m * G4 + n0 + tx * 4) = v;
    }
}

// ---------------------------------------------------------------------------
// Software grid barrier (sense-reversing, centralized). All NBLK CTAs are
// co-resident (1 CTA/SM). State returns to (count=0, sense=0) after an even
// number of phases -> deterministic across graph replays.
// ---------------------------------------------------------------------------
__device__ __forceinline__ void grid_barrier(unsigned& ls)
{
    __syncthreads();
    if (threadIdx.x == 0) {
        __threadfence();   // make this CTA's h writes visible before arriving
        unsigned old = atomicAdd(&g_bar_count, 1);
        if (old == NBLK - 1) {
            g_bar_count = 0;
            __threadfence();
            g_bar_sense = ls;          // release the phase
        } else {
            while (g_bar_sense != ls) { }
        }
        __threadfence();
    }
    __syncthreads();
    ls ^= 1u;
}

// ---------------------------------------------------------------------------
// Persistent per-layer LSTM recurrence, both directions.
// Grid: 128 CTAs = [dir(2) x colblock(64)], 8 hidden cols per CTA, 256 thr.
// Weights staged to SMEM ONCE; c lives in registers; h double-buffered in
// global by step parity; one grid barrier per timestep.
// ---------------------------------------------------------------------------
__device__ __forceinline__ float sigmoidf_(float x) { return 1.0f / (1.0f + expf(-x)); }

#define WST 516   // w_s row stride (floats): 516 % 32 == 4 -> conflict-free LDS.128

__global__ void __launch_bounds__(256) lstm_layer_kernel(
    const float* __restrict__ whh_f, const float* __restrict__ whh_b,
    float* __restrict__ outbuf)
{
    extern __shared__ float sm[];
    float* h_s = sm;                     // [32][512]          16384 floats
    float* w_s = sm + 32 * 512;          // [32][WST]          16512 floats
    float* g_s = w_s + 32 * WST;         // [32][33]            1056 floats

    const int dir  = blockIdx.x >> 6;
    const int cb   = blockIdx.x & 63;
    const int col0 = cb * 8;
    const int tid  = threadIdx.x;
    const int lane = tid & 31;
    const int wrp  = tid >> 5;
    const float* whh = dir ? whh_b : whh_f;

    // ---- stage 32 weight rows ONCE, row r = gate*8 + c ----
    {
        const int r    = lane;
        const int gate = r >> 3, c = r & 7;
        const float4* wp = (const float4*)(whh + ((size_t)gate * HH + col0 + c) * HH);
        const int seg = wrp;
#pragma unroll
        for (int j = 0; j < 16; j++) {
            float4 v = wp[seg * 16 + j];
            float* dst = w_s + r * WST + seg * 64 + j * 4;
            dst[0] = v.x; dst[1] = v.y; dst[2] = v.z; dst[3] = v.w;
        }
    }

    // update-role thread owns (ub, ucol); c kept in a register for all steps
    const int ub = tid >> 3, ucl = tid & 7, ucol = col0 + ucl;
    float c_reg = 0.0f;

    const int b0 = wrp * 4;
    const float4* wr4 = (const float4*)(w_s + lane * WST);   // conflict-free

    unsigned ls = 1u;

    for (int t = 0; t < SS; t++) {
        const int ph = t & 1;
        const int tt = dir ? (SS - 1 - t) : t;

        // ---- stage h_prev (L2 loads: __ldcg avoids stale L1 across barrier) ----
        {
            const float4* hp = (const float4*)&g_h[dir][ph][0][0];
            float4* hs = (float4*)h_s;
#pragma unroll
            for (int i = 0; i < 16; i++) hs[tid + i * 256] = __ldcg(hp + tid + i * 256);
        }
        __syncthreads();

        // ---- gates: warp wrp handles batches 4w..4w+3 (warp-uniform h
        //      broadcasts), lane indexes (gate = lane>>3, col = col0+(lane&7)) ----
        const float4* h0 = (const float4*)(h_s + (b0 + 0) * 512);
        const float4* h1 = (const float4*)(h_s + (b0 + 1) * 512);
        const float4* h2 = (const float4*)(h_s + (b0 + 2) * 512);
        const float4* h3 = (const float4*)(h_s + (b0 + 3) * 512);

        float acc0 = 0.f, acc1 = 0.f, acc2 = 0.f, acc3 = 0.f;
#pragma unroll 4
        for (int k4 = 0; k4 < 128; k4++) {
            float4 w = wr4[k4];
            float4 v;
            v = h0[k4]; acc0 += v.x * w.x + v.y * w.y + v.z * w.z + v.w * w.w;
            v = h1[k4]; acc1 += v.x * w.x + v.y * w.y + v.z * w.z + v.w * w.w;
            v = h2[k4]; acc2 += v.x * w.x + v.y * w.y + v.z * w.z + v.w * w.w;
            v = h3[k4]; acc3 += v.x * w.x + v.y * w.y + v.z * w.z + v.w * w.w;
        }

        // ---- add input projection, exchange through SMEM ----
        {
            const int gate = lane >> 3, cl = lane & 7;
            const int gr = gate * HH + col0 + cl;
            g_s[(b0 + 0) * 33 + lane] = acc0 + g_xp[dir][b0 + 0][tt][gr];
            g_s[(b0 + 1) * 33 + lane] = acc1 + g_xp[dir][b0 + 1][tt][gr];
            g_s[(b0 + 2) * 33 + lane] = acc2 + g_xp[dir][b0 + 2][tt][gr];
            g_s[(b0 + 3) * 33 + lane] = acc3 + g_xp[dir][b0 + 3][tt][gr];
        }
        __syncthreads();

        // ---- activations + state update ----
        {
            float gi = g_s[ub * 33 + 0  + ucl];
            float gf = g_s[ub * 33 + 8  + ucl];
            float gg = g_s[ub * 33 + 16 + ucl];
            float go = g_s[ub * 33 + 24 + ucl];
            float ii = sigmoidf_(gi);
            float ff = sigmoidf_(gf);
            float oo = sigmoidf_(go);
            float gt = tanhf(gg);
            c_reg = ff * c_reg + ii * gt;
            float h = oo * tanhf(c_reg);
            g_h[dir][ph ^ 1][ub][ucol] = h;
            outbuf[((size_t)ub * SS + tt) * (2 * HH) + dir * HH + ucol] = h;
        }

        // ---- grid barrier: all h writes visible before next step's reads ----
        grid_barrier(ls);
    }
}

// ---------------------------------------------------------------------------
// Launch: per layer — init, 2 xp GEMMs, 1 persistent recurrence. 8 graph nodes.
// ---------------------------------------------------------------------------
extern "C" void kernel_launch(void* const* d_in, const int* in_sizes, int n_in,
                              void* d_out, int out_size)
{
    (void)in_sizes; (void)n_in; (void)out_size;

    const float* x     = (const float*)d_in[0];
    const float* wihf0 = (const float*)d_in[1];
    const float* bihf0 = (const float*)d_in[2];
    const float* whhf0 = (const float*)d_in[3];
    const float* wihb0 = (const float*)d_in[4];
    const float* bihb0 = (const float*)d_in[5];
    const float* whhb0 = (const float*)d_in[6];
    const float* wihf1 = (const float*)d_in[7];
    const float* bihf1 = (const float*)d_in[8];
    const float* whhf1 = (const float*)d_in[9];
    const float* wihb1 = (const float*)d_in[10];
    const float* bihb1 = (const float*)d_in[11];
    const float* whhb1 = (const float*)d_in[12];
    float* out = (float*)d_out;

    void* p = nullptr;
    cudaGetSymbolAddress(&p, g_xp);
    float* xp = (float*)p;
    cudaGetSymbolAddress(&p, g_out0);
    float* out0 = (float*)p;

    const size_t STEP_SMEM = (size_t)(32 * 512 + 32 * WST + 32 * 33) * sizeof(float); // 135808 B
    cudaFuncSetAttribute(lstm_layer_kernel,
                         cudaFuncAttributeMaxDynamicSharedMemorySize, (int)STEP_SMEM);

    const dim3 ggrid(G4 / 64, (BB * SS) / 128);        // (32, 128)
    const size_t xp_stride = (size_t)BB * SS * G4;
    const int init_blocks = (2 * 2 * BB * HH + 255) / 256;

    // ---------- layer 0 (input dim = 512) ----------
    init_state_kernel<<<init_blocks, 256>>>();
    gemm_xp_kernel<<<ggrid, 256>>>(x, (long)SS * DD, (long)DD, DD, wihf0, bihf0, xp);
    gemm_xp_kernel<<<ggrid, 256>>>(x, (long)SS * DD, (long)DD, DD, wihb0, bihb0, xp + xp_stride);
    lstm_layer_kernel<<<NBLK, 256, STEP_SMEM>>>(whhf0, whhb0, out0);

    // ---------- layer 1 (input dim = 1024) ----------
    init_state_kernel<<<init_blocks, 256>>>();
    gemm_xp_kernel<<<ggrid, 256>>>(out0, (long)SS * 2 * HH, (long)(2 * HH), 2 * HH, wihf1, bihf1, xp);
    gemm_xp_kernel<<<ggrid, 256>>>(out0, (long)SS * 2 * HH, (long)(2 * HH), 2 * HH, wihb1, bihb1, xp + xp_stride);
    lstm_layer_kernel<<<NBLK, 256, STEP_SMEM>>>(whhf1, whhb1, out);
}

// round 8
// speedup vs baseline: 1.0609x; 1.0609x over previous
#include <cuda_runtime.h>
#include <cstddef>
#include <math.h>

// Problem constants
#define BB 32
#define SS 512
#define DD 512
#define HH 512
#define G4 (4 * HH)     // 2048
#define NBLK 128        // persistent grid size (1 CTA/SM, all co-resident)
#define NBLK_DIR 64     // CTAs per direction

// ---------------------------------------------------------------------------
// Packed fp32x2 helpers (Blackwell f32x2 pipe; ptxas never emits these)
// ---------------------------------------------------------------------------
__device__ __forceinline__ void fma2(unsigned long long& d,
                                     unsigned long long a, unsigned long long b)
{
    asm("fma.rn.f32x2 %0, %1, %2, %0;" : "+l"(d) : "l"(a), "l"(b));
}
__device__ __forceinline__ unsigned long long splat2(float x)
{
    unsigned long long r;
    asm("mov.b64 %0, {%1, %1};" : "=l"(r) : "f"(x));
    return r;
}
__device__ __forceinline__ float2 unpack2(unsigned long long v)
{
    float2 r;
    asm("mov.b64 {%0, %1}, %2;" : "=f"(r.x), "=f"(r.y) : "l"(v));
    return r;
}

// ---------------------------------------------------------------------------
// Scratch (static __device__ arrays — no allocation allowed)
// ---------------------------------------------------------------------------
__device__ float g_xp[2][BB][SS][G4];      // per-direction input projections
__device__ float g_out0[BB][SS][2 * HH];   // layer-0 output
__device__ float g_h[2][2][BB][HH];        // [dir][parity][b][h]
__device__ unsigned g_bar_count[2];
__device__ volatile unsigned g_bar_sense[2];

// ---------------------------------------------------------------------------
// Zero h state + barrier vars
// ---------------------------------------------------------------------------
__global__ void __launch_bounds__(256) init_state_kernel()
{
    int i = blockIdx.x * 256 + threadIdx.x;
    if (i < 2 * 2 * BB * HH) (&g_h[0][0][0][0])[i] = 0.0f;
    if (i < 2) { g_bar_count[i] = 0; g_bar_sense[i] = 0; }
}

// ---------------------------------------------------------------------------
// GEMM: out[m][n] = sum_k A(m,k) * W[n][k] + bias[n]
// Tile: 128(m) x 128(n) x 16(k), 256 threads, 8x8 micro-tile (FFMA2 packed
// over m-pairs), single-buffer smem + register prefetch of the next k-tile.
// M = 16384, N = 2048, K in {512,1024}.
// ---------------------------------------------------------------------------
__global__ void __launch_bounds__(256) gemm_xp_kernel(
    const float* __restrict__ A, long sAb, long sAs, int K,
    const float* __restrict__ W, const float* __restrict__ bias,
    float* __restrict__ out)
{
    __shared__ float As[16][132];   // [k][m], 528B rows (16B aligned)
    __shared__ float Bs[16][132];   // [k][n]

    const int tid = threadIdx.x;
    const int m0 = blockIdx.y * 128;
    const int n0 = blockIdx.x * 128;

    // A staging: 128 rows x 16 k -> 2 float4 per thread
    const int ar  = tid >> 1;
    const int ak  = (tid & 1) * 8;
    const int am  = m0 + ar;
    const int ab  = am >> 9;           // b (S = 512)
    const int asd = am & 511;          // s
    const float* Ap = A + (size_t)ab * sAb + (size_t)asd * sAs + ak;

    // B staging: 128 rows x 16 k -> 2 float4 per thread
    const int br = tid >> 1;
    const int bk = (tid & 1) * 8;
    const float* Wp = W + (size_t)(n0 + br) * K + bk;

    const int tx = tid & 15;           // n micro (8 cols)
    const int ty = tid >> 4;           // m micro (8 rows = 4 pairs)

    unsigned long long acc[4][8];      // [m-pair][n]
#pragma unroll
    for (int i = 0; i < 4; i++)
#pragma unroll
        for (int j = 0; j < 8; j++) acc[i][j] = 0ull;

    // prefetch first tile
    float4 a0 = *(const float4*)(Ap + 0);
    float4 a1 = *(const float4*)(Ap + 4);
    float4 b0 = *(const float4*)(Wp + 0);
    float4 b1 = *(const float4*)(Wp + 4);

    for (int k0 = 0; k0 < K; k0 += 16) {
        As[ak + 0][ar] = a0.x; As[ak + 1][ar] = a0.y; As[ak + 2][ar] = a0.z; As[ak + 3][ar] = a0.w;
        As[ak + 4][ar] = a1.x; As[ak + 5][ar] = a1.y; As[ak + 6][ar] = a1.z; As[ak + 7][ar] = a1.w;
        Bs[bk + 0][br] = b0.x; Bs[bk + 1][br] = b0.y; Bs[bk + 2][br] = b0.z; Bs[bk + 3][br] = b0.w;
        Bs[bk + 4][br] = b1.x; Bs[bk + 5][br] = b1.y; Bs[bk + 6][br] = b1.z; Bs[bk + 7][br] = b1.w;
        __syncthreads();

        if (k0 + 16 < K) {             // prefetch next tile
            a0 = *(const float4*)(Ap + k0 + 16);
            a1 = *(const float4*)(Ap + k0 + 20);
            b0 = *(const float4*)(Wp + k0 + 16);
            b1 = *(const float4*)(Wp + k0 + 20);
        }

#pragma unroll
        for (int k = 0; k < 16; k++) {
            // a: 4 m-pairs, naturally packed (m contiguous in As rows)
            const ulonglong2* arow = (const ulonglong2*)&As[k][ty * 8];
            ulonglong2 A01 = arow[0];  // pairs (m0,m1),(m2,m3)
            ulonglong2 A23 = arow[1];  // pairs (m4,m5),(m6,m7)
            unsigned long long ap[4] = {A01.x, A01.y, A23.x, A23.y};
            // b: 8 n values, splat each into both packed lanes
            float4 Bv0 = *(const float4*)&Bs[k][tx * 8];
            float4 Bv1 = *(const float4*)&Bs[k][tx * 8 + 4];
            unsigned long long bs[8] = {
                splat2(Bv0.x), splat2(Bv0.y), splat2(Bv0.z), splat2(Bv0.w),
                splat2(Bv1.x), splat2(Bv1.y), splat2(Bv1.z), splat2(Bv1.w)};
#pragma unroll
            for (int i = 0; i < 4; i++)
#pragma unroll
                for (int j = 0; j < 8; j++) fma2(acc[i][j], ap[i], bs[j]);
        }
        __syncthreads();
    }

    float4 bias0 = *(const float4*)(bias + n0 + tx * 8);
    float4 bias1 = *(const float4*)(bias + n0 + tx * 8 + 4);
#pragma unroll
    for (int mp = 0; mp < 4; mp++) {
        float2 r[8];
#pragma unroll
        for (int j = 0; j < 8; j++) r[j] = unpack2(acc[mp][j]);
        const int mlo = m0 + ty * 8 + 2 * mp;
        float* o0 = out + (size_t)mlo * G4 + n0 + tx * 8;
        float* o1 = o0 + G4;
        float4 v;
        v.x = r[0].x + bias0.x; v.y = r[1].x + bias0.y;
        v.z = r[2].x + bias0.z; v.w = r[3].x + bias0.w;
        *(float4*)(o0 + 0) = v;
        v.x = r[4].x + bias1.x; v.y = r[5].x + bias1.y;
        v.z = r[6].x + bias1.z; v.w = r[7].x + bias1.w;
        *(float4*)(o0 + 4) = v;
        v.x = r[0].y + bias0.x; v.y = r[1].y + bias0.y;
        v.z = r[2].y + bias0.z; v.w = r[3].y + bias0.w;
        *(float4*)(o1 + 0) = v;
        v.x = r[4].y + bias1.x; v.y = r[5].y + bias1.y;
        v.z = r[6].y + bias1.z; v.w = r[7].y + bias1.w;
        *(float4*)(o1 + 4) = v;
    }
}

// ---------------------------------------------------------------------------
// Software grid barrier, per direction (64 CTAs each, sense-reversing).
// State returns to (0,0) after an even number of phases -> replay-safe.
// ---------------------------------------------------------------------------
__device__ __forceinline__ void grid_barrier(int d, unsigned& ls)
{
    __syncthreads();
    if (threadIdx.x == 0) {
        __threadfence();
        unsigned old = atomicAdd(&g_bar_count[d], 1);
        if (old == NBLK_DIR - 1) {
            g_bar_count[d] = 0;
            __threadfence();
            g_bar_sense[d] = ls;
        } else {
            while (g_bar_sense[d] != ls) { }
        }
        __threadfence();
    }
    __syncthreads();
    ls ^= 1u;
}

// ---------------------------------------------------------------------------
// Persistent per-layer LSTM recurrence, both directions.
// Grid: 128 CTAs = [dir(2) x colblock(64)], 8 hidden cols per CTA, 256 thr.
// Roles: lane = gate-row (gate*8+col, 32 rows), warp = (batch-group of 8) x
// (k-half). Packed f32x2 dot products over k; partial sums for the two
// k-halves combined through SMEM. Weights staged ONCE; c in registers;
// h double-buffered in global; one per-direction grid barrier per step.
// ---------------------------------------------------------------------------
__device__ __forceinline__ float sigmoidf_(float x) { return 1.0f / (1.0f + expf(-x)); }

#define WST 516   // w_s row stride (floats): 16B-aligned rows, conflict-free LDS.128

__global__ void __launch_bounds__(256) lstm_layer_kernel(
    const float* __restrict__ whh_f, const float* __restrict__ whh_b,
    float* __restrict__ outbuf)
{
    extern __shared__ float sm[];
    float* h_s    = sm;                       // [32][512]       16384 floats
    float* w_s    = sm + 32 * 512;            // [32][WST]       16512 floats
    float* g_part = w_s + 32 * WST;           // [2][32][33]      2112 floats

    const int dir  = blockIdx.x >> 6;
    const int cb   = blockIdx.x & 63;
    const int col0 = cb * 8;
    const int tid  = threadIdx.x;
    const int lane = tid & 31;                // gate-row: gate = lane>>3, col = col0+(lane&7)
    const int wrp  = tid >> 5;
    const int bg   = wrp >> 1;                // batch group (8 batches)
    const int kh   = wrp & 1;                 // k half
    const int b0   = bg * 8;
    const int k4b  = kh * 64;                 // k4 (float4) base: half of 128
    const float* whh = dir ? whh_b : whh_f;

    // ---- stage 32 weight rows ONCE, row r = gate*8 + c ----
    {
        const int r    = lane;
        const int gate = r >> 3, c = r & 7;
        const float4* wp = (const float4*)(whh + ((size_t)gate * HH + col0 + c) * HH);
        const int seg = wrp;
#pragma unroll
        for (int j = 0; j < 16; j++) {
            float4 v = wp[seg * 16 + j];
            float* dst = w_s + r * WST + seg * 64 + j * 4;
            dst[0] = v.x; dst[1] = v.y; dst[2] = v.z; dst[3] = v.w;
        }
    }

    // update-role thread owns (ub, ucol); c kept in a register for all steps
    const int ub = tid >> 3, ucl = tid & 7, ucol = col0 + ucl;
    float c_reg = 0.0f;
    const float* xrow = &g_xp[dir][ub][0][0];

    const ulonglong2* wr2 = (const ulonglong2*)(w_s + lane * WST);  // k4-indexed

    unsigned ls = 1u;

    for (int t = 0; t < SS; t++) {
        const int ph = t & 1;
        const int tt = dir ? (SS - 1 - t) : t;

        // ---- prefetch input projections (independent of h) ----
        const size_t xo = (size_t)tt * G4 + ucol;
        float xi = __ldg(xrow + xo);
        float xf = __ldg(xrow + xo + HH);
        float xg = __ldg(xrow + xo + 2 * HH);
        float xo_ = __ldg(xrow + xo + 3 * HH);

        // ---- stage h_prev (L2 loads: __ldcg avoids stale L1 across barrier) ----
        {
            const float4* hp = (const float4*)&g_h[dir][ph][0][0];
            float4* hs = (float4*)h_s;
#pragma unroll
            for (int i = 0; i < 16; i++) hs[tid + i * 256] = __ldcg(hp + tid + i * 256);
        }
        __syncthreads();

        // ---- packed dot products: this warp does 8 batches x its k-half ----
        const ulonglong2* h0 = (const ulonglong2*)(h_s + (b0 + 0) * 512) + k4b;
        const ulonglong2* h1 = (const ulonglong2*)(h_s + (b0 + 1) * 512) + k4b;
        const ulonglong2* h2 = (const ulonglong2*)(h_s + (b0 + 2) * 512) + k4b;
        const ulonglong2* h3 = (const ulonglong2*)(h_s + (b0 + 3) * 512) + k4b;
        const ulonglong2* h4 = (const ulonglong2*)(h_s + (b0 + 4) * 512) + k4b;
        const ulonglong2* h5 = (const ulonglong2*)(h_s + (b0 + 5) * 512) + k4b;
        const ulonglong2* h6 = (const ulonglong2*)(h_s + (b0 + 6) * 512) + k4b;
        const ulonglong2* h7 = (const ulonglong2*)(h_s + (b0 + 7) * 512) + k4b;

        unsigned long long a0 = 0, a1 = 0, a2 = 0, a3 = 0,
                           a4 = 0, a5 = 0, a6 = 0, a7 = 0;
#pragma unroll 4
        for (int k4 = 0; k4 < 64; k4++) {
            ulonglong2 w = wr2[k4b + k4];
            ulonglong2 v;
            v = h0[k4]; fma2(a0, v.x, w.x); fma2(a0, v.y, w.y);
            v = h1[k4]; fma2(a1, v.x, w.x); fma2(a1, v.y, w.y);
            v = h2[k4]; fma2(a2, v.x, w.x); fma2(a2, v.y, w.y);
            v = h3[k4]; fma2(a3, v.x, w.x); fma2(a3, v.y, w.y);
            v = h4[k4]; fma2(a4, v.x, w.x); fma2(a4, v.y, w.y);
            v = h5[k4]; fma2(a5, v.x, w.x); fma2(a5, v.y, w.y);
            v = h6[k4]; fma2(a6, v.x, w.x); fma2(a6, v.y, w.y);
            v = h7[k4]; fma2(a7, v.x, w.x); fma2(a7, v.y, w.y);
        }

        // ---- write partial sums: g_part[kh][b][row] ----
        {
            float* gp = g_part + kh * (32 * 33);
            float2 p;
            p = unpack2(a0); gp[(b0 + 0) * 33 + lane] = p.x + p.y;
            p = unpack2(a1); gp[(b0 + 1) * 33 + lane] = p.x + p.y;
            p = unpack2(a2); gp[(b0 + 2) * 33 + lane] = p.x + p.y;
            p = unpack2(a3); gp[(b0 + 3) * 33 + lane] = p.x + p.y;
            p = unpack2(a4); gp[(b0 + 4) * 33 + lane] = p.x + p.y;
            p = unpack2(a5); gp[(b0 + 5) * 33 + lane] = p.x + p.y;
            p = unpack2(a6); gp[(b0 + 6) * 33 + lane] = p.x + p.y;
            p = unpack2(a7); gp[(b0 + 7) * 33 + lane] = p.x + p.y;
        }
        __syncthreads();

        // ---- activations + state update: 256 threads -> 32 b x 8 cols ----
        {
            const float* g0 = g_part + ub * 33;
            const float* g1 = g_part + 32 * 33 + ub * 33;
            float gi = g0[0  + ucl] + g1[0  + ucl] + xi;
            float gf = g0[8  + ucl] + g1[8  + ucl] + xf;
            float gg = g0[16 + ucl] + g1[16 + ucl] + xg;
            float go = g0[24 + ucl] + g1[24 + ucl] + xo_;
            float ii = sigmoidf_(gi);
            float ff = sigmoidf_(gf);
            float oo = sigmoidf_(go);
            float gt = tanhf(gg);
            c_reg = ff * c_reg + ii * gt;
            float h = oo * tanhf(c_reg);
            g_h[dir][ph ^ 1][ub][ucol] = h;
            outbuf[((size_t)ub * SS + tt) * (2 * HH) + dir * HH + ucol] = h;
        }

        // ---- per-direction grid barrier ----
        grid_barrier(dir, ls);
    }
}

// ---------------------------------------------------------------------------
// Launch: per layer — init, 2 xp GEMMs, 1 persistent recurrence. 8 graph nodes.
// ---------------------------------------------------------------------------
extern "C" void kernel_launch(void* const* d_in, const int* in_sizes, int n_in,
                              void* d_out, int out_size)
{
    (void)in_sizes; (void)n_in; (void)out_size;

    const float* x     = (const float*)d_in[0];
    const float* wihf0 = (const float*)d_in[1];
    const float* bihf0 = (const float*)d_in[2];
    const float* whhf0 = (const float*)d_in[3];
    const float* wihb0 = (const float*)d_in[4];
    const float* bihb0 = (const float*)d_in[5];
    const float* whhb0 = (const float*)d_in[6];
    const float* wihf1 = (const float*)d_in[7];
    const float* bihf1 = (const float*)d_in[8];
    const float* whhf1 = (const float*)d_in[9];
    const float* wihb1 = (const float*)d_in[10];
    const float* bihb1 = (const float*)d_in[11];
    const float* whhb1 = (const float*)d_in[12];
    float* out = (float*)d_out;

    void* p = nullptr;
    cudaGetSymbolAddress(&p, g_xp);
    float* xp = (float*)p;
    cudaGetSymbolAddress(&p, g_out0);
    float* out0 = (float*)p;

    const size_t STEP_SMEM = (size_t)(32 * 512 + 32 * WST + 2 * 32 * 33) * sizeof(float); // 140032 B
    cudaFuncSetAttribute(lstm_layer_kernel,
                         cudaFuncAttributeMaxDynamicSharedMemorySize, (int)STEP_SMEM);

    const dim3 ggrid(G4 / 128, (BB * SS) / 128);       // (16, 128)
    const size_t xp_stride = (size_t)BB * SS * G4;
    const int init_blocks = (2 * 2 * BB * HH + 255) / 256;

    // ---------- layer 0 (input dim = 512) ----------
    init_state_kernel<<<init_blocks, 256>>>();
    gemm_xp_kernel<<<ggrid, 256>>>(x, (long)SS * DD, (long)DD, DD, wihf0, bihf0, xp);
    gemm_xp_kernel<<<ggrid, 256>>>(x, (long)SS * DD, (long)DD, DD, wihb0, bihb0, xp + xp_stride);
    lstm_layer_kernel<<<NBLK, 256, STEP_SMEM>>>(whhf0, whhb0, out0);

    // ---------- layer 1 (input dim = 1024) ----------
    init_state_kernel<<<init_blocks, 256>>>();
    gemm_xp_kernel<<<ggrid, 256>>>(out0, (long)SS * 2 * HH, (long)(2 * HH), 2 * HH, wihf1, bihf1, xp);
    gemm_xp_kernel<<<ggrid, 256>>>(out0, (long)SS * 2 * HH, (long)(2 * HH), 2 * HH, wihb1, bihb1, xp + xp_stride);
    lstm_layer_kernel<<<NBLK, 256, STEP_SMEM>>>(whhf1, whhb1, out);
}

// round 9
// speedup vs baseline: 1.2411x; 1.1699x over previous
#include <cuda_runtime.h>
#include <cstddef>
#include <math.h>

// Problem constants
#define BB 32
#define SS 512
#define DD 512
#define HH 512
#define G4 (4 * HH)     // 2048
#define NBLK 128        // persistent grid size (1 CTA/SM, all co-resident)
#define NBLK_DIR 64     // CTAs per direction

// ---------------------------------------------------------------------------
// Packed fp32x2 helpers
// ---------------------------------------------------------------------------
__device__ __forceinline__ void fma2(unsigned long long& d,
                                     unsigned long long a, unsigned long long b)
{
    asm("fma.rn.f32x2 %0, %1, %2, %0;" : "+l"(d) : "l"(a), "l"(b));
}
__device__ __forceinline__ unsigned long long splat2(float x)
{
    unsigned long long r;
    asm("mov.b64 %0, {%1, %1};" : "=l"(r) : "f"(x));
    return r;
}
__device__ __forceinline__ float2 unpack2(unsigned long long v)
{
    float2 r;
    asm("mov.b64 {%0, %1}, %2;" : "=f"(r.x), "=f"(r.y) : "l"(v));
    return r;
}

// ---------------------------------------------------------------------------
// Scratch (static __device__ arrays — no allocation allowed)
// ---------------------------------------------------------------------------
__device__ float g_xp[2][SS][BB][G4];      // input projections, [dir][s][b][g]
__device__ float g_out0[BB][SS][2 * HH];   // layer-0 output
__device__ float g_h[2][2][BB][HH];        // [dir][parity][b][h]
__device__ unsigned g_bar_count[2];
__device__ volatile unsigned g_bar_sense[2];

// ---------------------------------------------------------------------------
// Zero h state + barrier vars
// ---------------------------------------------------------------------------
__global__ void __launch_bounds__(256) init_state_kernel()
{
    int i = blockIdx.x * 256 + threadIdx.x;
    if (i < 2 * 2 * BB * HH) (&g_h[0][0][0][0])[i] = 0.0f;
    if (i < 2) { g_bar_count[i] = 0; g_bar_sense[i] = 0; }
}

// ---------------------------------------------------------------------------
// GEMM: xp[s*BB+b][n] = sum_k A(b,s,k) * W[n][k] + bias[n]
// Tile: 128(m) x 128(n) x 16(k), 256 threads, 8x8 micro-tile (f32x2 packed
// over m-pairs), DOUBLE-BUFFERED smem, one __syncthreads per k-tile.
// Output layout: row (s*BB + b) — coalesced xp gathers in the recurrence.
// ---------------------------------------------------------------------------
__global__ void __launch_bounds__(256, 2) gemm_xp_kernel(
    const float* __restrict__ A, long sAb, long sAs, int K,
    const float* __restrict__ W, const float* __restrict__ bias,
    float* __restrict__ out)
{
    __shared__ float As[2][16][132];   // [buf][k][m]
    __shared__ float Bs[2][16][132];   // [buf][k][n]

    const int tid = threadIdx.x;
    const int m0 = blockIdx.y * 128;
    const int n0 = blockIdx.x * 128;

    // A staging: 128 rows x 16 k -> 2 float4 per thread
    const int ar  = tid >> 1;
    const int ak  = (tid & 1) * 8;
    const int am  = m0 + ar;
    const int ab  = am >> 9;           // b (S = 512)
    const int asd = am & 511;          // s
    const float* Ap = A + (size_t)ab * sAb + (size_t)asd * sAs + ak;

    // B staging: 128 rows x 16 k -> 2 float4 per thread
    const int br = tid >> 1;
    const int bk = (tid & 1) * 8;
    const float* Wp = W + (size_t)(n0 + br) * K + bk;

    const int tx = tid & 15;           // n micro (8 cols)
    const int ty = tid >> 4;           // m micro (8 rows = 4 pairs)

    unsigned long long acc[4][8];      // [m-pair][n]
#pragma unroll
    for (int i = 0; i < 4; i++)
#pragma unroll
        for (int j = 0; j < 8; j++) acc[i][j] = 0ull;

    // prefetch first tile into registers
    float4 a0 = *(const float4*)(Ap + 0);
    float4 a1 = *(const float4*)(Ap + 4);
    float4 b0 = *(const float4*)(Wp + 0);
    float4 b1 = *(const float4*)(Wp + 4);

    for (int k0 = 0; k0 < K; k0 += 16) {
        const int buf = (k0 >> 4) & 1;
        As[buf][ak + 0][ar] = a0.x; As[buf][ak + 1][ar] = a0.y;
        As[buf][ak + 2][ar] = a0.z; As[buf][ak + 3][ar] = a0.w;
        As[buf][ak + 4][ar] = a1.x; As[buf][ak + 5][ar] = a1.y;
        As[buf][ak + 6][ar] = a1.z; As[buf][ak + 7][ar] = a1.w;
        Bs[buf][bk + 0][br] = b0.x; Bs[buf][bk + 1][br] = b0.y;
        Bs[buf][bk + 2][br] = b0.z; Bs[buf][bk + 3][br] = b0.w;
        Bs[buf][bk + 4][br] = b1.x; Bs[buf][bk + 5][br] = b1.y;
        Bs[buf][bk + 6][br] = b1.z; Bs[buf][bk + 7][br] = b1.w;
        __syncthreads();

        if (k0 + 16 < K) {             // prefetch next tile (lands in regs)
            a0 = *(const float4*)(Ap + k0 + 16);
            a1 = *(const float4*)(Ap + k0 + 20);
            b0 = *(const float4*)(Wp + k0 + 16);
            b1 = *(const float4*)(Wp + k0 + 20);
        }

#pragma unroll
        for (int k = 0; k < 16; k++) {
            const ulonglong2* arow = (const ulonglong2*)&As[buf][k][ty * 8];
            ulonglong2 A01 = arow[0];
            ulonglong2 A23 = arow[1];
            unsigned long long ap[4] = {A01.x, A01.y, A23.x, A23.y};
            float4 Bv0 = *(const float4*)&Bs[buf][k][tx * 8];
            float4 Bv1 = *(const float4*)&Bs[buf][k][tx * 8 + 4];
            unsigned long long bsv[8] = {
                splat2(Bv0.x), splat2(Bv0.y), splat2(Bv0.z), splat2(Bv0.w),
                splat2(Bv1.x), splat2(Bv1.y), splat2(Bv1.z), splat2(Bv1.w)};
#pragma unroll
            for (int i = 0; i < 4; i++)
#pragma unroll
                for (int j = 0; j < 8; j++) fma2(acc[i][j], ap[i], bsv[j]);
        }
        // no second sync: next STS targets the other buffer
    }

    float4 bias0 = *(const float4*)(bias + n0 + tx * 8);
    float4 bias1 = *(const float4*)(bias + n0 + tx * 8 + 4);
#pragma unroll
    for (int mp = 0; mp < 4; mp++) {
        float2 r[8];
#pragma unroll
        for (int j = 0; j < 8; j++) r[j] = unpack2(acc[mp][j]);
        const int mlo = m0 + ty * 8 + 2 * mp;           // global m (b*SS + s)
        const int b_  = mlo >> 9;
        const int s_  = mlo & 511;
        float* o0 = out + ((size_t)s_ * BB + b_) * G4 + n0 + tx * 8;
        float* o1 = o0 + (size_t)BB * G4;               // next s (same b)
        float4 v;
        v.x = r[0].x + bias0.x; v.y = r[1].x + bias0.y;
        v.z = r[2].x + bias0.z; v.w = r[3].x + bias0.w;
        *(float4*)(o0 + 0) = v;
        v.x = r[4].x + bias1.x; v.y = r[5].x + bias1.y;
        v.z = r[6].x + bias1.z; v.w = r[7].x + bias1.w;
        *(float4*)(o0 + 4) = v;
        v.x = r[0].y + bias0.x; v.y = r[1].y + bias0.y;
        v.z = r[2].y + bias0.z; v.w = r[3].y + bias0.w;
        *(float4*)(o1 + 0) = v;
        v.x = r[4].y + bias1.x; v.y = r[5].y + bias1.y;
        v.z = r[6].y + bias1.z; v.w = r[7].y + bias1.w;
        *(float4*)(o1 + 4) = v;
    }
}

// ---------------------------------------------------------------------------
// Software grid barrier, per direction (64 CTAs each, sense-reversing).
// ---------------------------------------------------------------------------
__device__ __forceinline__ void grid_barrier(int d, unsigned& ls)
{
    __syncthreads();
    if (threadIdx.x == 0) {
        __threadfence();
        unsigned old = atomicAdd(&g_bar_count[d], 1);
        if (old == NBLK_DIR - 1) {
            g_bar_count[d] = 0;
            __threadfence();
            g_bar_sense[d] = ls;
        } else {
            while (g_bar_sense[d] != ls) { }
        }
        __threadfence();
    }
    __syncthreads();
    ls ^= 1u;
}

// ---------------------------------------------------------------------------
// Persistent per-layer LSTM recurrence, both directions.
// Grid: 128 CTAs = [dir(2) x colblock(64)], 8 hidden cols per CTA, 256 thr.
// Step = 32(b) x 32(r) x 512(k) GEMM. Thread (ks, bq, rq) owns a 4x4
// micro-tile: b = bq + 8i, r = rq + 8j, k-quarter ks. Every LDS.128 in a
// warp hits distinct banks (strides 516) -> 1 wavefront each, no broadcast
// waste. k-split x4 partials reduced via smem. Weights staged once; c in
// registers; h double-buffered in global; per-direction grid barrier.
// ---------------------------------------------------------------------------
__device__ __forceinline__ float sigmoidf_(float x) { return 1.0f / (1.0f + expf(-x)); }

#define HST 516   // h_s row stride (floats): 516 % 32 == 4 -> conflict-free
#define WST 516   // w_s row stride
#define PST 132   // p_s row stride (per batch: 32 rows x 4 ks)

__global__ void __launch_bounds__(256) lstm_layer_kernel(
    const float* __restrict__ whh_f, const float* __restrict__ whh_b,
    float* __restrict__ outbuf)
{
    extern __shared__ float sm[];
    float* h_s = sm;                      // [32][HST]   16512 floats
    float* w_s = sm + 32 * HST;           // [32][WST]   16512 floats
    float* p_s = w_s + 32 * WST;          // [32][PST]    4224 floats

    const int dir  = blockIdx.x >> 6;
    const int cb   = blockIdx.x & 63;
    const int col0 = cb * 8;
    const int tid  = threadIdx.x;
    const float* whh = dir ? whh_b : whh_f;

    // ---- stage 32 weight rows ONCE: row r = gate*8 + cl ----
#pragma unroll
    for (int i = 0; i < 16; i++) {
        int n = tid + i * 256;
        int r = n >> 7, k4 = n & 127;
        int gate = r >> 3, cl = r & 7;
        float4 v = *(const float4*)(whh + ((size_t)gate * HH + col0 + cl) * HH + k4 * 4);
        *(float4*)(w_s + r * WST + k4 * 4) = v;
    }

    // dot-phase roles
    const int ks = tid >> 6;              // k-quarter (128 k each)
    const int lo = tid & 63;
    const int bq = lo >> 3;               // 0..7
    const int rq = lo & 7;                // 0..7
    const int kk0 = ks * 32;              // ulonglong2 (8B-pair) base index

    // update-phase role: thread owns (ub, ucol); c kept in a register
    const int ub = tid >> 3, ucl = tid & 7, ucol = col0 + ucl;
    float c_reg = 0.0f;
    const float* xbase = &g_xp[dir][0][0][0];

    unsigned ls = 1u;

    for (int t = 0; t < SS; t++) {
        const int ph = t & 1;
        const int tt = dir ? (SS - 1 - t) : t;

        // ---- prefetch input projections (coalesced: [s][b][g] layout) ----
        const size_t xo = ((size_t)tt * BB + ub) * G4 + ucol;
        float xi  = __ldg(xbase + xo);
        float xf  = __ldg(xbase + xo + HH);
        float xg  = __ldg(xbase + xo + 2 * HH);
        float xo_ = __ldg(xbase + xo + 3 * HH);

        // ---- stage h_prev into padded smem (L2 loads bypass L1) ----
        {
            const float4* hp = (const float4*)&g_h[dir][ph][0][0];
#pragma unroll
            for (int i = 0; i < 16; i++) {
                int n = tid + i * 256;
                float4 v = __ldcg(hp + n);
                int b = n >> 7, k4 = n & 127;
                *(float4*)(h_s + b * HST + k4 * 4) = v;
            }
        }
        __syncthreads();

        // ---- 4x4 register micro-tile over this thread's k-quarter ----
        const ulonglong2* h0 = (const ulonglong2*)(h_s + (bq     ) * HST) + kk0;
        const ulonglong2* h1 = (const ulonglong2*)(h_s + (bq +  8) * HST) + kk0;
        const ulonglong2* h2 = (const ulonglong2*)(h_s + (bq + 16) * HST) + kk0;
        const ulonglong2* h3 = (const ulonglong2*)(h_s + (bq + 24) * HST) + kk0;
        const ulonglong2* w0 = (const ulonglong2*)(w_s + (rq     ) * WST) + kk0;
        const ulonglong2* w1 = (const ulonglong2*)(w_s + (rq +  8) * WST) + kk0;
        const ulonglong2* w2 = (const ulonglong2*)(w_s + (rq + 16) * WST) + kk0;
        const ulonglong2* w3 = (const ulonglong2*)(w_s + (rq + 24) * WST) + kk0;

        unsigned long long acc[4][4];
#pragma unroll
        for (int i = 0; i < 4; i++)
#pragma unroll
            for (int j = 0; j < 4; j++) acc[i][j] = 0ull;

#pragma unroll 4
        for (int k4 = 0; k4 < 32; k4++) {
            ulonglong2 H0 = h0[k4], H1 = h1[k4], H2 = h2[k4], H3 = h3[k4];
            ulonglong2 W0 = w0[k4], W1 = w1[k4], W2 = w2[k4], W3 = w3[k4];
            fma2(acc[0][0], H0.x, W0.x); fma2(acc[0][0], H0.y, W0.y);
            fma2(acc[0][1], H0.x, W1.x); fma2(acc[0][1], H0.y, W1.y);
            fma2(acc[0][2], H0.x, W2.x); fma2(acc[0][2], H0.y, W2.y);
            fma2(acc[0][3], H0.x, W3.x); fma2(acc[0][3], H0.y, W3.y);
            fma2(acc[1][0], H1.x, W0.x); fma2(acc[1][0], H1.y, W0.y);
            fma2(acc[1][1], H1.x, W1.x); fma2(acc[1][1], H1.y, W1.y);
            fma2(acc[1][2], H1.x, W2.x); fma2(acc[1][2], H1.y, W2.y);
            fma2(acc[1][3], H1.x, W3.x); fma2(acc[1][3], H1.y, W3.y);
            fma2(acc[2][0], H2.x, W0.x); fma2(acc[2][0], H2.y, W0.y);
            fma2(acc[2][1], H2.x, W1.x); fma2(acc[2][1], H2.y, W1.y);
            fma2(acc[2][2], H2.x, W2.x); fma2(acc[2][2], H2.y, W2.y);
            fma2(acc[2][3], H2.x, W3.x); fma2(acc[2][3], H2.y, W3.y);
            fma2(acc[3][0], H3.x, W0.x); fma2(acc[3][0], H3.y, W0.y);
            fma2(acc[3][1], H3.x, W1.x); fma2(acc[3][1], H3.y, W1.y);
            fma2(acc[3][2], H3.x, W2.x); fma2(acc[3][2], H3.y, W2.y);
            fma2(acc[3][3], H3.x, W3.x); fma2(acc[3][3], H3.y, W3.y);
        }

        // ---- write k-quarter partials: p_s[b][r*4 + ks] ----
#pragma unroll
        for (int i = 0; i < 4; i++)
#pragma unroll
            for (int j = 0; j < 4; j++) {
                float2 p = unpack2(acc[i][j]);
                p_s[(bq + 8 * i) * PST + (rq + 8 * j) * 4 + ks] = p.x + p.y;
            }
        __syncthreads();

        // ---- activations + state update: 256 threads -> 32 b x 8 cols ----
        {
            float gs[4];
#pragma unroll
            for (int g = 0; g < 4; g++) {
                int r = g * 8 + ucl;
                float4 p4 = *(const float4*)(p_s + ub * PST + r * 4);
                gs[g] = (p4.x + p4.y) + (p4.z + p4.w);
            }
            float ii = sigmoidf_(gs[0] + xi);
            float ff = sigmoidf_(gs[1] + xf);
            float gt = tanhf(gs[2] + xg);
            float oo = sigmoidf_(gs[3] + xo_);
            c_reg = ff * c_reg + ii * gt;
            float h = oo * tanhf(c_reg);
            g_h[dir][ph ^ 1][ub][ucol] = h;
            outbuf[((size_t)ub * SS + tt) * (2 * HH) + dir * HH + ucol] = h;
        }

        // ---- per-direction grid barrier (also separates p_s/h_s phases) ----
        grid_barrier(dir, ls);
    }
}

// ---------------------------------------------------------------------------
// Launch: per layer — init, 2 xp GEMMs, 1 persistent recurrence. 8 graph nodes.
// ---------------------------------------------------------------------------
extern "C" void kernel_launch(void* const* d_in, const int* in_sizes, int n_in,
                              void* d_out, int out_size)
{
    (void)in_sizes; (void)n_in; (void)out_size;

    const float* x     = (const float*)d_in[0];
    const float* wihf0 = (const float*)d_in[1];
    const float* bihf0 = (const float*)d_in[2];
    const float* whhf0 = (const float*)d_in[3];
    const float* wihb0 = (const float*)d_in[4];
    const float* bihb0 = (const float*)d_in[5];
    const float* whhb0 = (const float*)d_in[6];
    const float* wihf1 = (const float*)d_in[7];
    const float* bihf1 = (const float*)d_in[8];
    const float* whhf1 = (const float*)d_in[9];
    const float* wihb1 = (const float*)d_in[10];
    const float* bihb1 = (const float*)d_in[11];
    const float* whhb1 = (const float*)d_in[12];
    float* out = (float*)d_out;

    void* p = nullptr;
    cudaGetSymbolAddress(&p, g_xp);
    float* xp = (float*)p;
    cudaGetSymbolAddress(&p, g_out0);
    float* out0 = (float*)p;

    const size_t STEP_SMEM = (size_t)(32 * HST + 32 * WST + 32 * PST) * sizeof(float); // 148992 B
    cudaFuncSetAttribute(lstm_layer_kernel,
                         cudaFuncAttributeMaxDynamicSharedMemorySize, (int)STEP_SMEM);

    const dim3 ggrid(G4 / 128, (BB * SS) / 128);       // (16, 128)
    const size_t xp_stride = (size_t)SS * BB * G4;     // dir stride in g_xp
    const int init_blocks = (2 * 2 * BB * HH + 255) / 256;

    // ---------- layer 0 (input dim = 512) ----------
    init_state_kernel<<<init_blocks, 256>>>();
    gemm_xp_kernel<<<ggrid, 256>>>(x, (long)SS * DD, (long)DD, DD, wihf0, bihf0, xp);
    gemm_xp_kernel<<<ggrid, 256>>>(x, (long)SS * DD, (long)DD, DD, wihb0, bihb0, xp + xp_stride);
    lstm_layer_kernel<<<NBLK, 256, STEP_SMEM>>>(whhf0, whhb0, out0);

    // ---------- layer 1 (input dim = 1024) ----------
    init_state_kernel<<<init_blocks, 256>>>();
    gemm_xp_kernel<<<ggrid, 256>>>(out0, (long)SS * 2 * HH, (long)(2 * HH), 2 * HH, wihf1, bihf1, xp);
    gemm_xp_kernel<<<ggrid, 256>>>(out0, (long)SS * 2 * HH, (long)(2 * HH), 2 * HH, wihb1, bihb1, xp + xp_stride);
    lstm_layer_kernel<<<NBLK, 256, STEP_SMEM>>>(whhf1, whhb1, out);
}

// round 10
// speedup vs baseline: 1.2991x; 1.0467x over previous
#include <cuda_runtime.h>
#include <cstddef>
#include <math.h>

// Problem constants
#define BB 32
#define SS 512
#define DD 512
#define HH 512
#define G4 (4 * HH)     // 2048
#define NBLK 128        // persistent grid size (1 CTA/SM, all co-resident)
#define NBLK_DIR 64     // CTAs per direction
#define NT 512          // recurrence CTA threads

// ---------------------------------------------------------------------------
// Packed fp32x2 helpers
// ---------------------------------------------------------------------------
__device__ __forceinline__ void fma2(unsigned long long& d,
                                     unsigned long long a, unsigned long long b)
{
    asm("fma.rn.f32x2 %0, %1, %2, %0;" : "+l"(d) : "l"(a), "l"(b));
}
__device__ __forceinline__ unsigned long long splat2(float x)
{
    unsigned long long r;
    asm("mov.b64 %0, {%1, %1};" : "=l"(r) : "f"(x));
    return r;
}
__device__ __forceinline__ float2 unpack2(unsigned long long v)
{
    float2 r;
    asm("mov.b64 {%0, %1}, %2;" : "=f"(r.x), "=f"(r.y) : "l"(v));
    return r;
}

// ---------------------------------------------------------------------------
// Scratch (static __device__ arrays — no allocation allowed)
// ---------------------------------------------------------------------------
__device__ float g_xp[2][SS][BB][G4];      // input projections, [dir][s][b][g]
__device__ float g_out0[BB][SS][2 * HH];   // layer-0 output
__device__ float g_h[2][2][BB][HH];        // [dir][parity][b][h]
__device__ unsigned g_bar_count[2];
__device__ volatile unsigned g_bar_sense[2];

// ---------------------------------------------------------------------------
// Zero h state + barrier vars
// ---------------------------------------------------------------------------
__global__ void __launch_bounds__(256) init_state_kernel()
{
    int i = blockIdx.x * 256 + threadIdx.x;
    if (i < 2 * 2 * BB * HH) (&g_h[0][0][0][0])[i] = 0.0f;
    if (i < 2) { g_bar_count[i] = 0; g_bar_sense[i] = 0; }
}

// ---------------------------------------------------------------------------
// GEMM: xp[s*BB+b][n] = sum_k A(b,s,k) * W[n][k] + bias[n]
// Tile: 128(m) x 128(n) x 16(k), 256 threads, 8x8 micro-tile (f32x2 packed
// over m-pairs), double-buffered smem, one __syncthreads per k-tile.
// Micro-tile fragments split into two CONTIGUOUS 4-wide groups (x*4 and
// 64 + x*4) so every fragment LDS.128 is a dense 256B/warp access (2 wf).
// ---------------------------------------------------------------------------
__global__ void __launch_bounds__(256, 2) gemm_xp_kernel(
    const float* __restrict__ A, long sAb, long sAs, int K,
    const float* __restrict__ W, const float* __restrict__ bias,
    float* __restrict__ out)
{
    __shared__ float As[2][16][132];   // [buf][k][m]
    __shared__ float Bs[2][16][132];   // [buf][k][n]

    const int tid = threadIdx.x;
    const int m0 = blockIdx.y * 128;
    const int n0 = blockIdx.x * 128;

    // A staging: 128 rows x 16 k -> 2 float4 per thread
    const int ar  = tid >> 1;
    const int ak  = (tid & 1) * 8;
    const int am  = m0 + ar;
    const int ab  = am >> 9;           // b (S = 512)
    const int asd = am & 511;          // s
    const float* Ap = A + (size_t)ab * sAb + (size_t)asd * sAs + ak;

    // B staging: 128 rows x 16 k -> 2 float4 per thread
    const int br = tid >> 1;
    const int bk = (tid & 1) * 8;
    const float* Wp = W + (size_t)(n0 + br) * K + bk;

    const int tx = tid & 15;           // n micro: cols tx*4.. and 64+tx*4..
    const int ty = tid >> 4;           // m micro: rows ty*4.. and 64+ty*4..

    unsigned long long acc[4][8];      // [m-pair: g0p0,g0p1,g1p0,g1p1][n]
#pragma unroll
    for (int i = 0; i < 4; i++)
#pragma unroll
        for (int j = 0; j < 8; j++) acc[i][j] = 0ull;

    // prefetch first tile into registers
    float4 a0 = *(const float4*)(Ap + 0);
    float4 a1 = *(const float4*)(Ap + 4);
    float4 b0 = *(const float4*)(Wp + 0);
    float4 b1 = *(const float4*)(Wp + 4);

    for (int k0 = 0; k0 < K; k0 += 16) {
        const int buf = (k0 >> 4) & 1;
        As[buf][ak + 0][ar] = a0.x; As[buf][ak + 1][ar] = a0.y;
        As[buf][ak + 2][ar] = a0.z; As[buf][ak + 3][ar] = a0.w;
        As[buf][ak + 4][ar] = a1.x; As[buf][ak + 5][ar] = a1.y;
        As[buf][ak + 6][ar] = a1.z; As[buf][ak + 7][ar] = a1.w;
        Bs[buf][bk + 0][br] = b0.x; Bs[buf][bk + 1][br] = b0.y;
        Bs[buf][bk + 2][br] = b0.z; Bs[buf][bk + 3][br] = b0.w;
        Bs[buf][bk + 4][br] = b1.x; Bs[buf][bk + 5][br] = b1.y;
        Bs[buf][bk + 6][br] = b1.z; Bs[buf][bk + 7][br] = b1.w;
        __syncthreads();

        if (k0 + 16 < K) {             // prefetch next tile (lands in regs)
            a0 = *(const float4*)(Ap + k0 + 16);
            a1 = *(const float4*)(Ap + k0 + 20);
            b0 = *(const float4*)(Wp + k0 + 16);
            b1 = *(const float4*)(Wp + k0 + 20);
        }

#pragma unroll
        for (int k = 0; k < 16; k++) {
            ulonglong2 Alo = *(const ulonglong2*)&As[buf][k][ty * 4];
            ulonglong2 Ahi = *(const ulonglong2*)&As[buf][k][64 + ty * 4];
            unsigned long long ap[4] = {Alo.x, Alo.y, Ahi.x, Ahi.y};
            float4 Blo = *(const float4*)&Bs[buf][k][tx * 4];
            float4 Bhi = *(const float4*)&Bs[buf][k][64 + tx * 4];
            unsigned long long bsv[8] = {
                splat2(Blo.x), splat2(Blo.y), splat2(Blo.z), splat2(Blo.w),
                splat2(Bhi.x), splat2(Bhi.y), splat2(Bhi.z), splat2(Bhi.w)};
#pragma unroll
            for (int i = 0; i < 4; i++)
#pragma unroll
                for (int j = 0; j < 8; j++) fma2(acc[i][j], ap[i], bsv[j]);
        }
        // no second sync: next STS targets the other buffer
    }

    float4 biaslo = *(const float4*)(bias + n0 + tx * 4);
    float4 biashi = *(const float4*)(bias + n0 + 64 + tx * 4);
#pragma unroll
    for (int mp = 0; mp < 4; mp++) {
        float2 r[8];
#pragma unroll
        for (int j = 0; j < 8; j++) r[j] = unpack2(acc[mp][j]);
        const int mg = mp >> 1, pp = mp & 1;
        const int mlo = m0 + mg * 64 + ty * 4 + 2 * pp;  // global m (b*SS + s)
        const int b_  = mlo >> 9;
        const int s_  = mlo & 511;
        float* o0 = out + ((size_t)s_ * BB + b_) * G4 + n0;
        float* o1 = o0 + (size_t)BB * G4;                // next s (same b)
        float4 v;
        v.x = r[0].x + biaslo.x; v.y = r[1].x + biaslo.y;
        v.z = r[2].x + biaslo.z; v.w = r[3].x + biaslo.w;
        *(float4*)(o0 + tx * 4) = v;
        v.x = r[4].x + biashi.x; v.y = r[5].x + biashi.y;
        v.z = r[6].x + biashi.z; v.w = r[7].x + biashi.w;
        *(float4*)(o0 + 64 + tx * 4) = v;
        v.x = r[0].y + biaslo.x; v.y = r[1].y + biaslo.y;
        v.z = r[2].y + biaslo.z; v.w = r[3].y + biaslo.w;
        *(float4*)(o1 + tx * 4) = v;
        v.x = r[4].y + biashi.x; v.y = r[5].y + biashi.y;
        v.z = r[6].y + biashi.z; v.w = r[7].y + biashi.w;
        *(float4*)(o1 + 64 + tx * 4) = v;
    }
}

// ---------------------------------------------------------------------------
// Software grid barrier, per direction (64 CTAs each, sense-reversing).
// ---------------------------------------------------------------------------
__device__ __forceinline__ void grid_barrier(int d, unsigned& ls)
{
    __syncthreads();
    if (threadIdx.x == 0) {
        __threadfence();
        unsigned old = atomicAdd(&g_bar_count[d], 1);
        if (old == NBLK_DIR - 1) {
            g_bar_count[d] = 0;
            __threadfence();
            g_bar_sense[d] = ls;
        } else {
            while (g_bar_sense[d] != ls) { }
        }
        __threadfence();
    }
    __syncthreads();
    ls ^= 1u;
}

// ---------------------------------------------------------------------------
// Persistent per-layer LSTM recurrence, both directions.
// Grid: 128 CTAs = [dir(2) x colblock(64)], 8 hidden cols per CTA, 512 thr.
// Step = 32(b) x 32(r) x 512(k) GEMM. Thread (ks, bq, rq) owns a 4x4
// micro-tile over its k-eighth (64 k). All dot-phase LDS.128 conflict-free
// (row stride 516). k-split x8 partials reduced via smem. Weights staged
// once; c in registers; h double-buffered in global; per-dir grid barrier.
// 16 warps/CTA for latency hiding (FFMA2/LDS floors are thread-count
// invariant; the stall component is not).
// ---------------------------------------------------------------------------
__device__ __forceinline__ float sigmoidf_(float x) { return 1.0f / (1.0f + expf(-x)); }

#define HST 516   // h_s row stride (floats)
#define WST 516   // w_s row stride
#define PST 260   // p_s row stride: 32 r * 8 ks + pad

__global__ void __launch_bounds__(NT) lstm_layer_kernel(
    const float* __restrict__ whh_f, const float* __restrict__ whh_b,
    float* __restrict__ outbuf)
{
    extern __shared__ float sm[];
    float* h_s = sm;                      // [32][HST]   16512 floats
    float* w_s = sm + 32 * HST;           // [32][WST]   16512 floats
    float* p_s = w_s + 32 * WST;          // [32][PST]    8320 floats

    const int dir  = blockIdx.x >> 6;
    const int cb   = blockIdx.x & 63;
    const int col0 = cb * 8;
    const int tid  = threadIdx.x;
    const float* whh = dir ? whh_b : whh_f;

    // ---- stage 32 weight rows ONCE: row r = gate*8 + cl ----
#pragma unroll
    for (int i = 0; i < 8; i++) {
        int n = tid + i * NT;
        int r = n >> 7, k4 = n & 127;
        int gate = r >> 3, cl = r & 7;
        float4 v = *(const float4*)(whh + ((size_t)gate * HH + col0 + cl) * HH + k4 * 4);
        *(float4*)(w_s + r * WST + k4 * 4) = v;
    }

    // dot-phase roles: k-eighth x (bq, rq)
    const int ks = tid >> 6;              // 0..7 (64 k each)
    const int lo = tid & 63;
    const int bq = lo >> 3;               // 0..7
    const int rq = lo & 7;                // 0..7
    const int kk0 = ks * 16;              // ulonglong2 (16B) base index

    // update-phase role (threads 0..255): thread owns (ub, ucol)
    const int ub = tid >> 3, ucl = tid & 7, ucol = col0 + ucl;
    float c_reg = 0.0f;
    const float* xbase = &g_xp[dir][0][0][0];

    unsigned ls = 1u;

    for (int t = 0; t < SS; t++) {
        const int ph = t & 1;
        const int tt = dir ? (SS - 1 - t) : t;

        // ---- prefetch input projections (coalesced; update threads only) ----
        float xi = 0.f, xf = 0.f, xg = 0.f, xo_ = 0.f;
        if (tid < 256) {
            const size_t xo = ((size_t)tt * BB + ub) * G4 + ucol;
            xi  = __ldg(xbase + xo);
            xf  = __ldg(xbase + xo + HH);
            xg  = __ldg(xbase + xo + 2 * HH);
            xo_ = __ldg(xbase + xo + 3 * HH);
        }

        // ---- stage h_prev into padded smem (L2 loads bypass L1) ----
        {
            const float4* hp = (const float4*)&g_h[dir][ph][0][0];
#pragma unroll
            for (int i = 0; i < 8; i++) {
                int n = tid + i * NT;
                float4 v = __ldcg(hp + n);
                int b = n >> 7, k4 = n & 127;
                *(float4*)(h_s + b * HST + k4 * 4) = v;
            }
        }
        __syncthreads();

        // ---- 4x4 register micro-tile over this thread's k-eighth ----
        const ulonglong2* h0 = (const ulonglong2*)(h_s + (bq     ) * HST) + kk0;
        const ulonglong2* h1 = (const ulonglong2*)(h_s + (bq +  8) * HST) + kk0;
        const ulonglong2* h2 = (const ulonglong2*)(h_s + (bq + 16) * HST) + kk0;
        const ulonglong2* h3 = (const ulonglong2*)(h_s + (bq + 24) * HST) + kk0;
        const ulonglong2* w0 = (const ulonglong2*)(w_s + (rq     ) * WST) + kk0;
        const ulonglong2* w1 = (const ulonglong2*)(w_s + (rq +  8) * WST) + kk0;
        const ulonglong2* w2 = (const ulonglong2*)(w_s + (rq + 16) * WST) + kk0;
        const ulonglong2* w3 = (const ulonglong2*)(w_s + (rq + 24) * WST) + kk0;

        unsigned long long acc[4][4];
#pragma unroll
        for (int i = 0; i < 4; i++)
#pragma unroll
            for (int j = 0; j < 4; j++) acc[i][j] = 0ull;

#pragma unroll 4
        for (int k4 = 0; k4 < 16; k4++) {
            ulonglong2 H0 = h0[k4], H1 = h1[k4], H2 = h2[k4], H3 = h3[k4];
            ulonglong2 W0 = w0[k4], W1 = w1[k4], W2 = w2[k4], W3 = w3[k4];
            fma2(acc[0][0], H0.x, W0.x); fma2(acc[0][0], H0.y, W0.y);
            fma2(acc[0][1], H0.x, W1.x); fma2(acc[0][1], H0.y, W1.y);
            fma2(acc[0][2], H0.x, W2.x); fma2(acc[0][2], H0.y, W2.y);
            fma2(acc[0][3], H0.x, W3.x); fma2(acc[0][3], H0.y, W3.y);
            fma2(acc[1][0], H1.x, W0.x); fma2(acc[1][0], H1.y, W0.y);
            fma2(acc[1][1], H1.x, W1.x); fma2(acc[1][1], H1.y, W1.y);
            fma2(acc[1][2], H1.x, W2.x); fma2(acc[1][2], H1.y, W2.y);
            fma2(acc[1][3], H1.x, W3.x); fma2(acc[1][3], H1.y, W3.y);
            fma2(acc[2][0], H2.x, W0.x); fma2(acc[2][0], H2.y, W0.y);
            fma2(acc[2][1], H2.x, W1.x); fma2(acc[2][1], H2.y, W1.y);
            fma2(acc[2][2], H2.x, W2.x); fma2(acc[2][2], H2.y, W2.y);
            fma2(acc[2][3], H2.x, W3.x); fma2(acc[2][3], H2.y, W3.y);
            fma2(acc[3][0], H3.x, W0.x); fma2(acc[3][0], H3.y, W0.y);
            fma2(acc[3][1], H3.x, W1.x); fma2(acc[3][1], H3.y, W1.y);
            fma2(acc[3][2], H3.x, W2.x); fma2(acc[3][2], H3.y, W2.y);
            fma2(acc[3][3], H3.x, W3.x); fma2(acc[3][3], H3.y, W3.y);
        }

        // ---- write k-eighth partials: p_s[b][r*8 + ks] ----
#pragma unroll
        for (int i = 0; i < 4; i++)
#pragma unroll
            for (int j = 0; j < 4; j++) {
                float2 p = unpack2(acc[i][j]);
                p_s[(bq + 8 * i) * PST + (rq + 8 * j) * 8 + ks] = p.x + p.y;
            }
        __syncthreads();

        // ---- activations + state update: threads 0..255 -> 32 b x 8 cols ----
        if (tid < 256) {
            float gs[4];
#pragma unroll
            for (int g = 0; g < 4; g++) {
                int r = g * 8 + ucl;
                float4 p0 = *(const float4*)(p_s + ub * PST + r * 8);
                float4 p1 = *(const float4*)(p_s + ub * PST + r * 8 + 4);
                gs[g] = ((p0.x + p0.y) + (p0.z + p0.w))
                      + ((p1.x + p1.y) + (p1.z + p1.w));
            }
            float ii = sigmoidf_(gs[0] + xi);
            float ff = sigmoidf_(gs[1] + xf);
            float gt = tanhf(gs[2] + xg);
            float oo = sigmoidf_(gs[3] + xo_);
            c_reg = ff * c_reg + ii * gt;
            float h = oo * tanhf(c_reg);
            g_h[dir][ph ^ 1][ub][ucol] = h;
            outbuf[((size_t)ub * SS + tt) * (2 * HH) + dir * HH + ucol] = h;
        }

        // ---- per-direction grid barrier (also separates p_s/h_s phases) ----
        grid_barrier(dir, ls);
    }
}

// ---------------------------------------------------------------------------
// Launch: per layer — init, 2 xp GEMMs, 1 persistent recurrence. 8 graph nodes.
// ---------------------------------------------------------------------------
extern "C" void kernel_launch(void* const* d_in, const int* in_sizes, int n_in,
                              void* d_out, int out_size)
{
    (void)in_sizes; (void)n_in; (void)out_size;

    const float* x     = (const float*)d_in[0];
    const float* wihf0 = (const float*)d_in[1];
    const float* bihf0 = (const float*)d_in[2];
    const float* whhf0 = (const float*)d_in[3];
    const float* wihb0 = (const float*)d_in[4];
    const float* bihb0 = (const float*)d_in[5];
    const float* whhb0 = (const float*)d_in[6];
    const float* wihf1 = (const float*)d_in[7];
    const float* bihf1 = (const float*)d_in[8];
    const float* whhf1 = (const float*)d_in[9];
    const float* wihb1 = (const float*)d_in[10];
    const float* bihb1 = (const float*)d_in[11];
    const float* whhb1 = (const float*)d_in[12];
    float* out = (float*)d_out;

    void* p = nullptr;
    cudaGetSymbolAddress(&p, g_xp);
    float* xp = (float*)p;
    cudaGetSymbolAddress(&p, g_out0);
    float* out0 = (float*)p;

    const size_t STEP_SMEM = (size_t)(32 * HST + 32 * WST + 32 * PST) * sizeof(float); // 165376 B
    cudaFuncSetAttribute(lstm_layer_kernel,
                         cudaFuncAttributeMaxDynamicSharedMemorySize, (int)STEP_SMEM);

    const dim3 ggrid(G4 / 128, (BB * SS) / 128);       // (16, 128)
    const size_t xp_stride = (size_t)SS * BB * G4;     // dir stride in g_xp
    const int init_blocks = (2 * 2 * BB * HH + 255) / 256;

    // ---------- layer 0 (input dim = 512) ----------
    init_state_kernel<<<init_blocks, 256>>>();
    gemm_xp_kernel<<<ggrid, 256>>>(x, (long)SS * DD, (long)DD, DD, wihf0, bihf0, xp);
    gemm_xp_kernel<<<ggrid, 256>>>(x, (long)SS * DD, (long)DD, DD, wihb0, bihb0, xp + xp_stride);
    lstm_layer_kernel<<<NBLK, NT, STEP_SMEM>>>(whhf0, whhb0, out0);

    // ---------- layer 1 (input dim = 1024) ----------
    init_state_kernel<<<init_blocks, 256>>>();
    gemm_xp_kernel<<<ggrid, 256>>>(out0, (long)SS * 2 * HH, (long)(2 * HH), 2 * HH, wihf1, bihf1, xp);
    gemm_xp_kernel<<<ggrid, 256>>>(out0, (long)SS * 2 * HH, (long)(2 * HH), 2 * HH, wihb1, bihb1, xp + xp_stride);
    lstm_layer_kernel<<<NBLK, NT, STEP_SMEM>>>(whhf1, whhb1, out);
}

// round 12
// speedup vs baseline: 1.5393x; 1.1849x over previous
#include <cuda_runtime.h>
#include <cuda_bf16.h>
#include <cstdint>
#include <cstddef>
#include <math.h>

// Problem constants
#define BB 32
#define SS 512
#define DD 512
#define HH 512
#define G4 (4 * HH)     // 2048
#define NBLK 128        // persistent grid size (recurrence)
#define NBLK_DIR 64     // CTAs per direction
#define NT 512          // recurrence CTA threads

// ===========================================================================
// Small helpers
// ===========================================================================
__device__ __forceinline__ uint32_t smem_u32(const void* p)
{
    uint32_t a;
    asm("{ .reg .u64 t; cvta.to.shared.u64 t, %1; cvt.u32.u64 %0, t; }"
        : "=r"(a) : "l"(p));
    return a;
}

// ldmatrix x4 (four 8x8 b16 matrices)
__device__ __forceinline__ void ldsm4(uint32_t& r0, uint32_t& r1,
                                      uint32_t& r2, uint32_t& r3, uint32_t addr)
{
    asm volatile("ldmatrix.sync.aligned.m8n8.x4.shared.b16 {%0,%1,%2,%3}, [%4];"
                 : "=r"(r0), "=r"(r1), "=r"(r2), "=r"(r3) : "r"(addr));
}

// mma m16n8k16 bf16 -> f32
__device__ __forceinline__ void mma16816(float* c, const uint32_t* a,
                                         const uint32_t* b)
{
    asm volatile(
        "mma.sync.aligned.m16n8k16.row.col.f32.bf16.bf16.f32 "
        "{%0,%1,%2,%3}, {%4,%5,%6,%7}, {%8,%9}, {%0,%1,%2,%3};"
        : "+f"(c[0]), "+f"(c[1]), "+f"(c[2]), "+f"(c[3])
        : "r"(a[0]), "r"(a[1]), "r"(a[2]), "r"(a[3]), "r"(b[0]), "r"(b[1]));
}

__device__ __forceinline__ void cp_async16(uint32_t dst, const void* src)
{
    asm volatile("cp.async.cg.shared.global [%0], [%1], 16;"
                 :: "r"(dst), "l"(src) : "memory");
}

// Packed fp32x2 helpers (recurrence)
__device__ __forceinline__ void fma2(unsigned long long& d,
                                     unsigned long long a, unsigned long long b)
{
    asm("fma.rn.f32x2 %0, %1, %2, %0;" : "+l"(d) : "l"(a), "l"(b));
}
__device__ __forceinline__ float2 unpack2(unsigned long long v)
{
    float2 r;
    asm("mov.b64 {%0, %1}, %2;" : "=f"(r.x), "=f"(r.y) : "l"(v));
    return r;
}

// ===========================================================================
// Scratch (static __device__ arrays — no allocation allowed)
// ===========================================================================
__device__ float g_xp[2][SS][BB][G4];            // input projections [dir][s][b][g]
__device__ float g_out0[BB][SS][2 * HH];         // layer-0 output
__device__ float g_h[2][2][BB][HH];              // [dir][parity][b][h]
__device__ unsigned g_bar_count[2];
__device__ volatile unsigned g_bar_sense[2];
__device__ __nv_bfloat16 g_a_hi[16384 * 1024];   // A hi (max K=1024)
__device__ __nv_bfloat16 g_a_lo[16384 * 1024];   // A lo
__device__ __nv_bfloat16 g_w_hi[2][G4 * 1024];   // W hi per direction
__device__ __nv_bfloat16 g_w_lo[2][G4 * 1024];   // W lo per direction

// ---------------------------------------------------------------------------
// Zero h state + barrier vars
// ---------------------------------------------------------------------------
__global__ void __launch_bounds__(256) init_state_kernel()
{
    int i = blockIdx.x * 256 + threadIdx.x;
    if (i < 2 * 2 * BB * HH) (&g_h[0][0][0][0])[i] = 0.0f;
    if (i < 2) { g_bar_count[i] = 0; g_bar_sense[i] = 0; }
}

// ---------------------------------------------------------------------------
// fp32 -> bf16 (hi, lo) split: x ≈ hi + lo, lo = rn(x - hi)
// ---------------------------------------------------------------------------
__global__ void __launch_bounds__(256) conv_pair_kernel(
    const float* __restrict__ src,
    __nv_bfloat16* __restrict__ hi, __nv_bfloat16* __restrict__ lo, int n4)
{
    int i = blockIdx.x * 256 + threadIdx.x;
    if (i >= n4) return;
    float4 v = ((const float4*)src)[i];
    __nv_bfloat16 h0 = __float2bfloat16(v.x);
    __nv_bfloat16 h1 = __float2bfloat16(v.y);
    __nv_bfloat16 h2 = __float2bfloat16(v.z);
    __nv_bfloat16 h3 = __float2bfloat16(v.w);
    __nv_bfloat16 l0 = __float2bfloat16(v.x - __bfloat162float(h0));
    __nv_bfloat16 l1 = __float2bfloat16(v.y - __bfloat162float(h1));
    __nv_bfloat16 l2 = __float2bfloat16(v.z - __bfloat162float(h2));
    __nv_bfloat16 l3 = __float2bfloat16(v.w - __bfloat162float(h3));
    ((__nv_bfloat162*)hi)[2 * i]     = __halves2bfloat162(h0, h1);
    ((__nv_bfloat162*)hi)[2 * i + 1] = __halves2bfloat162(h2, h3);
    ((__nv_bfloat162*)lo)[2 * i]     = __halves2bfloat162(l0, l1);
    ((__nv_bfloat162*)lo)[2 * i + 1] = __halves2bfloat162(l2, l3);
}

// ===========================================================================
// Tensor-core GEMM via mma.sync (3xBF16):
//   out[s*BB+b][n] = sum_k A(m,k)*W(n,k) + bias[n],  m = b*SS + s
// CTA 128(m) x 128(n), 8 warps (2x4), warp tile 64x32, K-chunks of 32.
// smem tiles [128][40] bf16 (stride 40: conflict-free ldmatrix, 16B-aligned
// rows). cp.async 2-deep pipeline. Accumulate Ahi*Bhi + Ahi*Blo + Alo*Bhi.
// ===========================================================================
#define KC 32
#define TST 40                               // bf16 row stride (80 bytes)
#define TILE_B (128 * TST * 2)               // 10240 bytes per tile
#define BUFB (4 * TILE_B)                    // Ahi, Alo, Bhi, Blo = 40960
#define GSMEM (2 * BUFB)                     // 81920

__global__ void __launch_bounds__(256, 2) gemm_tc_kernel(
    const __nv_bfloat16* __restrict__ Ahi, const __nv_bfloat16* __restrict__ Alo,
    const __nv_bfloat16* __restrict__ Whi, const __nv_bfloat16* __restrict__ Wlo,
    const float* __restrict__ bias, float* __restrict__ out, int K)
{
    extern __shared__ char smem[];
    const int tid = threadIdx.x;
    const int wid = tid >> 5, lane = tid & 31;
    const int wm = wid >> 2, wn = wid & 3;       // 2 x 4 warp grid
    const int m0 = blockIdx.y * 128, n0 = blockIdx.x * 128;
    const uint32_t sb = smem_u32(smem);
    const int nch = K / KC;

    // staging role: thread -> (row, two uint4 slots)
    const int srow = tid >> 1;                   // 0..127
    const int sj   = (tid & 1) * 2;              // uint4 index 0 or 2
    const __nv_bfloat16* gbase[4] = {
        Ahi + (size_t)m0 * K, Alo + (size_t)m0 * K,
        Whi + (size_t)n0 * K, Wlo + (size_t)n0 * K };

    float acc[4][4][4];
#pragma unroll
    for (int i = 0; i < 4; i++)
#pragma unroll
        for (int j = 0; j < 4; j++)
#pragma unroll
            for (int r = 0; r < 4; r++) acc[i][j][r] = 0.0f;

    // ---- issue chunk c into buffer (c & 1) ----
    auto issue = [&](int c) {
        const uint32_t dst0 = sb + (c & 1) * BUFB + srow * 80 + sj * 16;
        const size_t go = (size_t)srow * K + c * KC + sj * 8;
#pragma unroll
        for (int t = 0; t < 4; t++) {
            cp_async16(dst0 + t * TILE_B,      gbase[t] + go);
            cp_async16(dst0 + t * TILE_B + 16, gbase[t] + go + 8);
        }
        asm volatile("cp.async.commit_group;" ::: "memory");
    };

    issue(0);
    if (nch > 1) issue(1);

    // ldmatrix address components (per lane)
    const uint32_t a_row = wm * 64 + (lane & 15);       // + i*16
    const uint32_t a_ko  = (lane >> 4) * 8;             // + kk*16
    const uint32_t b_n   = wn * 32 + ((lane >> 4) << 3) + (lane & 7);  // + jj*16
    const uint32_t b_ko  = ((lane >> 3) & 1) * 8;       // + kk*16

    for (int c = 0; c < nch; c++) {
        if (c + 1 < nch) asm volatile("cp.async.wait_group 1;" ::: "memory");
        else             asm volatile("cp.async.wait_group 0;" ::: "memory");
        __syncthreads();

        const uint32_t ah = sb + (c & 1) * BUFB;
        const uint32_t al = ah + TILE_B;
        const uint32_t bh = ah + 2 * TILE_B;
        const uint32_t bl = ah + 3 * TILE_B;

#pragma unroll
        for (int kk = 0; kk < 2; kk++) {
            // B fragments: 4 n-frags (2 regs each), hi and lo
            uint32_t Bh[8], Bl[8];
#pragma unroll
            for (int jj = 0; jj < 2; jj++) {
                uint32_t addr = (b_n + jj * 16) * 80 + (kk * 16 + b_ko) * 2;
                ldsm4(Bh[4 * jj], Bh[4 * jj + 1], Bh[4 * jj + 2], Bh[4 * jj + 3], bh + addr);
                ldsm4(Bl[4 * jj], Bl[4 * jj + 1], Bl[4 * jj + 2], Bl[4 * jj + 3], bl + addr);
            }
#pragma unroll
            for (int i = 0; i < 4; i++) {
                uint32_t addr = (a_row + i * 16) * 80 + (kk * 16 + a_ko) * 2;
                uint32_t Ah[4], Al[4];
                ldsm4(Ah[0], Ah[1], Ah[2], Ah[3], ah + addr);
                ldsm4(Al[0], Al[1], Al[2], Al[3], al + addr);
#pragma unroll
                for (int j = 0; j < 4; j++) {
                    mma16816(acc[i][j], Ah, Bh + 2 * j);
                    mma16816(acc[i][j], Ah, Bl + 2 * j);
                    mma16816(acc[i][j], Al, Bh + 2 * j);
                }
            }
        }
        __syncthreads();
        if (c + 2 < nch) issue(c + 2);
    }

    // ---- epilogue: add bias, write to xp [s][b][g] layout ----
#pragma unroll
    for (int i = 0; i < 4; i++) {
        const int r = m0 + wm * 64 + i * 16 + (lane >> 2);   // m = b*SS + s
        const int s_ = r & 511, b_ = r >> 9;
        float* p0 = out + ((size_t)s_ * BB + b_) * G4;
        float* p1 = p0 + (size_t)8 * BB * G4;                // row r+8 -> s+8
#pragma unroll
        for (int j = 0; j < 4; j++) {
            const int col = n0 + wn * 32 + j * 8 + (lane & 3) * 2;
            float2 bv = *(const float2*)(bias + col);
            float2 v0 = { acc[i][j][0] + bv.x, acc[i][j][1] + bv.y };
            float2 v1 = { acc[i][j][2] + bv.x, acc[i][j][3] + bv.y };
            *(float2*)(p0 + col) = v0;
            *(float2*)(p1 + col) = v1;
        }
    }
}

// ---------------------------------------------------------------------------
// Software grid barrier, per direction (64 CTAs each, sense-reversing).
// ---------------------------------------------------------------------------
__device__ __forceinline__ void grid_barrier(int d, unsigned& ls)
{
    __syncthreads();
    if (threadIdx.x == 0) {
        __threadfence();
        unsigned old = atomicAdd(&g_bar_count[d], 1);
        if (old == NBLK_DIR - 1) {
            g_bar_count[d] = 0;
            __threadfence();
            g_bar_sense[d] = ls;
        } else {
            while (g_bar_sense[d] != ls) { }
        }
        __threadfence();
    }
    __syncthreads();
    ls ^= 1u;
}

// ---------------------------------------------------------------------------
// Persistent per-layer LSTM recurrence (unchanged from R10, passing).
// ---------------------------------------------------------------------------
__device__ __forceinline__ float sigmoidf_(float x) { return 1.0f / (1.0f + expf(-x)); }

#define HST 516
#define WST 516
#define PST 260

__global__ void __launch_bounds__(NT) lstm_layer_kernel(
    const float* __restrict__ whh_f, const float* __restrict__ whh_b,
    float* __restrict__ outbuf)
{
    extern __shared__ float sm[];
    float* h_s = sm;                      // [32][HST]
    float* w_s = sm + 32 * HST;           // [32][WST]
    float* p_s = w_s + 32 * WST;          // [32][PST]

    const int dir  = blockIdx.x >> 6;
    const int cb   = blockIdx.x & 63;
    const int col0 = cb * 8;
    const int tid  = threadIdx.x;
    const float* whh = dir ? whh_b : whh_f;

#pragma unroll
    for (int i = 0; i < 8; i++) {
        int n = tid + i * NT;
        int r = n >> 7, k4 = n & 127;
        int gate = r >> 3, cl = r & 7;
        float4 v = *(const float4*)(whh + ((size_t)gate * HH + col0 + cl) * HH + k4 * 4);
        *(float4*)(w_s + r * WST + k4 * 4) = v;
    }

    const int ks = tid >> 6;
    const int lo = tid & 63;
    const int bq = lo >> 3;
    const int rq = lo & 7;
    const int kk0 = ks * 16;

    const int ub = tid >> 3, ucl = tid & 7, ucol = col0 + ucl;
    float c_reg = 0.0f;
    const float* xbase = &g_xp[dir][0][0][0];

    unsigned ls = 1u;

    for (int t = 0; t < SS; t++) {
        const int ph = t & 1;
        const int tt = dir ? (SS - 1 - t) : t;

        float xi = 0.f, xf = 0.f, xg = 0.f, xo_ = 0.f;
        if (tid < 256) {
            const size_t xo = ((size_t)tt * BB + ub) * G4 + ucol;
            xi  = __ldg(xbase + xo);
            xf  = __ldg(xbase + xo + HH);
            xg  = __ldg(xbase + xo + 2 * HH);
            xo_ = __ldg(xbase + xo + 3 * HH);
        }

        {
            const float4* hp = (const float4*)&g_h[dir][ph][0][0];
#pragma unroll
            for (int i = 0; i < 8; i++) {
                int n = tid + i * NT;
                float4 v = __ldcg(hp + n);
                int b = n >> 7, k4 = n & 127;
                *(float4*)(h_s + b * HST + k4 * 4) = v;
            }
        }
        __syncthreads();

        const ulonglong2* h0 = (const ulonglong2*)(h_s + (bq     ) * HST) + kk0;
        const ulonglong2* h1 = (const ulonglong2*)(h_s + (bq +  8) * HST) + kk0;
        const ulonglong2* h2 = (const ulonglong2*)(h_s + (bq + 16) * HST) + kk0;
        const ulonglong2* h3 = (const ulonglong2*)(h_s + (bq + 24) * HST) + kk0;
        const ulonglong2* w0 = (const ulonglong2*)(w_s + (rq     ) * WST) + kk0;
        const ulonglong2* w1 = (const ulonglong2*)(w_s + (rq +  8) * WST) + kk0;
        const ulonglong2* w2 = (const ulonglong2*)(w_s + (rq + 16) * WST) + kk0;
        const ulonglong2* w3 = (const ulonglong2*)(w_s + (rq + 24) * WST) + kk0;

        unsigned long long acc[4][4];
#pragma unroll
        for (int i = 0; i < 4; i++)
#pragma unroll
            for (int j = 0; j < 4; j++) acc[i][j] = 0ull;

#pragma unroll 4
        for (int k4 = 0; k4 < 16; k4++) {
            ulonglong2 H0 = h0[k4], H1 = h1[k4], H2 = h2[k4], H3 = h3[k4];
            ulonglong2 W0 = w0[k4], W1 = w1[k4], W2 = w2[k4], W3 = w3[k4];
            fma2(acc[0][0], H0.x, W0.x); fma2(acc[0][0], H0.y, W0.y);
            fma2(acc[0][1], H0.x, W1.x); fma2(acc[0][1], H0.y, W1.y);
            fma2(acc[0][2], H0.x, W2.x); fma2(acc[0][2], H0.y, W2.y);
            fma2(acc[0][3], H0.x, W3.x); fma2(acc[0][3], H0.y, W3.y);
            fma2(acc[1][0], H1.x, W0.x); fma2(acc[1][0], H1.y, W0.y);
            fma2(acc[1][1], H1.x, W1.x); fma2(acc[1][1], H1.y, W1.y);
            fma2(acc[1][2], H1.x, W2.x); fma2(acc[1][2], H1.y, W2.y);
            fma2(acc[1][3], H1.x, W3.x); fma2(acc[1][3], H1.y, W3.y);
            fma2(acc[2][0], H2.x, W0.x); fma2(acc[2][0], H2.y, W0.y);
            fma2(acc[2][1], H2.x, W1.x); fma2(acc[2][1], H2.y, W1.y);
            fma2(acc[2][2], H2.x, W2.x); fma2(acc[2][2], H2.y, W2.y);
            fma2(acc[2][3], H2.x, W3.x); fma2(acc[2][3], H2.y, W3.y);
            fma2(acc[3][0], H3.x, W0.x); fma2(acc[3][0], H3.y, W0.y);
            fma2(acc[3][1], H3.x, W1.x); fma2(acc[3][1], H3.y, W1.y);
            fma2(acc[3][2], H3.x, W2.x); fma2(acc[3][2], H3.y, W2.y);
            fma2(acc[3][3], H3.x, W3.x); fma2(acc[3][3], H3.y, W3.y);
        }

#pragma unroll
        for (int i = 0; i < 4; i++)
#pragma unroll
            for (int j = 0; j < 4; j++) {
                float2 p = unpack2(acc[i][j]);
                p_s[(bq + 8 * i) * PST + (rq + 8 * j) * 8 + ks] = p.x + p.y;
            }
        __syncthreads();

        if (tid < 256) {
            float gs[4];
#pragma unroll
            for (int g = 0; g < 4; g++) {
                int r = g * 8 + ucl;
                float4 p0 = *(const float4*)(p_s + ub * PST + r * 8);
                float4 p1 = *(const float4*)(p_s + ub * PST + r * 8 + 4);
                gs[g] = ((p0.x + p0.y) + (p0.z + p0.w))
                      + ((p1.x + p1.y) + (p1.z + p1.w));
            }
            float ii = sigmoidf_(gs[0] + xi);
            float ff = sigmoidf_(gs[1] + xf);
            float gt = tanhf(gs[2] + xg);
            float oo = sigmoidf_(gs[3] + xo_);
            c_reg = ff * c_reg + ii * gt;
            float h = oo * tanhf(c_reg);
            g_h[dir][ph ^ 1][ub][ucol] = h;
            outbuf[((size_t)ub * SS + tt) * (2 * HH) + dir * HH + ucol] = h;
        }

        grid_barrier(dir, ls);
    }
}

// ===========================================================================
// Launch: per layer — init, 3 conversions, 2 mma GEMMs, 1 recurrence.
// ===========================================================================
extern "C" void kernel_launch(void* const* d_in, const int* in_sizes, int n_in,
                              void* d_out, int out_size)
{
    (void)in_sizes; (void)n_in; (void)out_size;

    const float* x     = (const float*)d_in[0];
    const float* wihf0 = (const float*)d_in[1];
    const float* bihf0 = (const float*)d_in[2];
    const float* whhf0 = (const float*)d_in[3];
    const float* wihb0 = (const float*)d_in[4];
    const float* bihb0 = (const float*)d_in[5];
    const float* whhb0 = (const float*)d_in[6];
    const float* wihf1 = (const float*)d_in[7];
    const float* bihf1 = (const float*)d_in[8];
    const float* whhf1 = (const float*)d_in[9];
    const float* wihb1 = (const float*)d_in[10];
    const float* bihb1 = (const float*)d_in[11];
    const float* whhb1 = (const float*)d_in[12];
    float* out = (float*)d_out;

    void* p = nullptr;
    cudaGetSymbolAddress(&p, g_xp);    float* xp   = (float*)p;
    cudaGetSymbolAddress(&p, g_out0);  float* out0 = (float*)p;
    cudaGetSymbolAddress(&p, g_a_hi);  __nv_bfloat16* ahi = (__nv_bfloat16*)p;
    cudaGetSymbolAddress(&p, g_a_lo);  __nv_bfloat16* alo = (__nv_bfloat16*)p;
    cudaGetSymbolAddress(&p, g_w_hi);  __nv_bfloat16* whi = (__nv_bfloat16*)p;
    cudaGetSymbolAddress(&p, g_w_lo);  __nv_bfloat16* wlo = (__nv_bfloat16*)p;

    const size_t STEP_SMEM = (size_t)(32 * HST + 32 * WST + 32 * PST) * sizeof(float);
    cudaFuncSetAttribute(lstm_layer_kernel,
                         cudaFuncAttributeMaxDynamicSharedMemorySize, (int)STEP_SMEM);
    cudaFuncSetAttribute(gemm_tc_kernel,
                         cudaFuncAttributeMaxDynamicSharedMemorySize, GSMEM);

    const dim3 tgrid(G4 / 128, (BB * SS) / 128);       // (16, 128)
    const size_t xp_stride = (size_t)SS * BB * G4;     // dir stride in g_xp
    const size_t wst = (size_t)G4 * 1024;              // dir stride in g_w_*
    const int init_blocks = (2 * 2 * BB * HH + 255) / 256;

    // ---------- layer 0 (K = 512) ----------
    init_state_kernel<<<init_blocks, 256>>>();
    conv_pair_kernel<<<(BB * SS * DD / 4 + 255) / 256, 256>>>(x, ahi, alo, BB * SS * DD / 4);
    conv_pair_kernel<<<(G4 * DD / 4 + 255) / 256, 256>>>(wihf0, whi, wlo, G4 * DD / 4);
    conv_pair_kernel<<<(G4 * DD / 4 + 255) / 256, 256>>>(wihb0, whi + wst, wlo + wst, G4 * DD / 4);
    gemm_tc_kernel<<<tgrid, 256, GSMEM>>>(ahi, alo, whi, wlo, bihf0, xp, DD);
    gemm_tc_kernel<<<tgrid, 256, GSMEM>>>(ahi, alo, whi + wst, wlo + wst, bihb0, xp + xp_stride, DD);
    lstm_layer_kernel<<<NBLK, NT, STEP_SMEM>>>(whhf0, whhb0, out0);

    // ---------- layer 1 (K = 1024) ----------
    init_state_kernel<<<init_blocks, 256>>>();
    conv_pair_kernel<<<(BB * SS * 2 * HH / 4 + 255) / 256, 256>>>(out0, ahi, alo, BB * SS * 2 * HH / 4);
    conv_pair_kernel<<<(G4 * 2 * HH / 4 + 255) / 256, 256>>>(wihf1, whi, wlo, G4 * 2 * HH / 4);
    conv_pair_kernel<<<(G4 * 2 * HH / 4 + 255) / 256, 256>>>(wihb1, whi + wst, wlo + wst, G4 * 2 * HH / 4);
    gemm_tc_kernel<<<tgrid, 256, GSMEM>>>(ahi, alo, whi, wlo, bihf1, xp, 2 * HH);
    gemm_tc_kernel<<<tgrid, 256, GSMEM>>>(ahi, alo, whi + wst, wlo + wst, bihb1, xp + xp_stride, 2 * HH);
    lstm_layer_kernel<<<NBLK, NT, STEP_SMEM>>>(whhf1, whhb1, out);
}